// round 5
// baseline (speedup 1.0000x reference)
#include <cuda_runtime.h>
#include <cuda_bf16.h>
#include <cstdint>

#define NV 50000
#define NE_MAX 400000
#define H 128

// Scratch (no cudaMalloc allowed)
__device__ float g_agg[(size_t)NV * H];        // 25.6 MB (written, not accumulated)
__device__ int   g_cnt[NV];
__device__ int   g_rowptr[NV + 1];
__device__ int   g_cursor[NV];
__device__ int   g_col[2 * NE_MAX];            // 3.2 MB

// ---------------------------------------------------------------------------
// 1. zero counters (only 200 KB now)
// ---------------------------------------------------------------------------
__global__ void k_zero_cnt() {
    int i = blockIdx.x * blockDim.x + threadIdx.x;
    if (i < NV) g_cnt[i] = 0;
}

// ---------------------------------------------------------------------------
// 2. histogram: every element of edge_idx is a dst exactly once (symmetrized)
// ---------------------------------------------------------------------------
__global__ void k_hist(const int* __restrict__ ei, int total) {
    int i = blockIdx.x * blockDim.x + threadIdx.x;
    int i4 = i * 4;
    if (i4 + 3 < total) {
        int4 v = *reinterpret_cast<const int4*>(ei + i4);
        atomicAdd(&g_cnt[v.x], 1);
        atomicAdd(&g_cnt[v.y], 1);
        atomicAdd(&g_cnt[v.z], 1);
        atomicAdd(&g_cnt[v.w], 1);
    } else {
        for (int j = i4; j < total; j++) atomicAdd(&g_cnt[ei[j]], 1);
    }
}

// ---------------------------------------------------------------------------
// 3. exclusive scan over 50k counts, single CTA of 1024 threads
// ---------------------------------------------------------------------------
#define SCAN_CH 49   // 1024 * 49 = 50176 >= NV
__global__ __launch_bounds__(1024)
void k_scan() {
    __shared__ int ssum[1024];
    int t = threadIdx.x;
    int base = t * SCAN_CH;

    int s = 0;
#pragma unroll 4
    for (int i = 0; i < SCAN_CH; i++) {
        int idx = base + i;
        if (idx < NV) s += g_cnt[idx];
    }
    ssum[t] = s;
    __syncthreads();
    // Hillis-Steele inclusive scan
    for (int off = 1; off < 1024; off <<= 1) {
        int v = (t >= off) ? ssum[t - off] : 0;
        __syncthreads();
        ssum[t] += v;
        __syncthreads();
    }
    int run = ssum[t] - s;   // exclusive prefix for this thread's chunk
    for (int i = 0; i < SCAN_CH; i++) {
        int idx = base + i;
        if (idx < NV) {
            int c = g_cnt[idx];
            g_rowptr[idx] = run;
            g_cursor[idx] = run;
            run += c;
        }
    }
    if (t == 1023) g_rowptr[NV] = ssum[1023];
}

// ---------------------------------------------------------------------------
// 4. fill column lists: one thread per undirected edge, both directions
// ---------------------------------------------------------------------------
__global__ void k_fill(const int* __restrict__ ei, int nE) {
    int i = blockIdx.x * blockDim.x + threadIdx.x;
    if (i >= nE) return;
    int a = ei[i];
    int b = ei[nE + i];
    int p1 = atomicAdd(&g_cursor[b], 1);
    g_col[p1] = a;                         // edge a->b contributes x[a] to agg[b]
    int p2 = atomicAdd(&g_cursor[a], 1);
    g_col[p2] = b;                         // edge b->a contributes x[b] to agg[a]
}

// ---------------------------------------------------------------------------
// 5. gather: warp per vertex, pure reads, no atomics
// ---------------------------------------------------------------------------
__global__ __launch_bounds__(256)
void k_gather(const float* __restrict__ x) {
    int v    = (int)(((unsigned)blockIdx.x * blockDim.x + threadIdx.x) >> 5);
    int lane = threadIdx.x & 31;
    if (v >= NV) return;

    int beg = g_rowptr[v];
    int end = g_rowptr[v + 1];

    float4 acc = make_float4(0.f, 0.f, 0.f, 0.f);
    for (int j = beg; j < end; j += 32) {
        int n = min(32, end - j);
        int u = (j + lane < end) ? g_col[j + lane] : 0;
#pragma unroll 4
        for (int k = 0; k < n; k++) {
            int uu = __shfl_sync(0xffffffffu, u, k);
            float4 t = reinterpret_cast<const float4*>(x + (size_t)uu * H)[lane];
            acc.x += t.x; acc.y += t.y; acc.z += t.z; acc.w += t.w;
        }
    }
    reinterpret_cast<float4*>(g_agg + (size_t)v * H)[lane] = acc;
}

// ---------------------------------------------------------------------------
// 6. HMMA GEMM (same as R4): out = [agg | deg*x] @ W^T, bf16 hi/lo split
// ---------------------------------------------------------------------------
#define BK 32
#define PITCH 40

__device__ __forceinline__ uint32_t pack_bf2(float a, float b) {
    __nv_bfloat162 h = __floats2bfloat162_rn(a, b);
    return *reinterpret_cast<uint32_t*>(&h);
}

__device__ __forceinline__ void mma_16816(float* c, const uint32_t* a,
                                          uint32_t b0, uint32_t b1) {
    asm volatile(
        "mma.sync.aligned.m16n8k16.row.col.f32.bf16.bf16.f32 "
        "{%0,%1,%2,%3}, {%4,%5,%6,%7}, {%8,%9}, {%0,%1,%2,%3};"
        : "+f"(c[0]), "+f"(c[1]), "+f"(c[2]), "+f"(c[3])
        : "r"(a[0]), "r"(a[1]), "r"(a[2]), "r"(a[3]), "r"(b0), "r"(b1));
}

__global__ __launch_bounds__(256)
void k_gemm(const float* __restrict__ x, const float* __restrict__ W,
            float* __restrict__ out) {
    __shared__ __align__(16) __nv_bfloat16 Ahi[128][PITCH];
    __shared__ __align__(16) __nv_bfloat16 Alo[128][PITCH];
    __shared__ __align__(16) __nv_bfloat16 Bhi[128][PITCH];
    __shared__ __align__(16) __nv_bfloat16 Blo[128][PITCH];

    const int tid    = threadIdx.x;
    const int wid    = tid >> 5;
    const int lane   = tid & 31;
    const int grp    = lane >> 2;
    const int tig    = lane & 3;
    const int warp_m = wid & 3;
    const int warp_n = wid >> 2;
    const int row0   = blockIdx.x * 128;

    float acc[2][8][4];
#pragma unroll
    for (int mi = 0; mi < 2; mi++)
#pragma unroll
        for (int ni = 0; ni < 8; ni++)
#pragma unroll
            for (int q = 0; q < 4; q++) acc[mi][ni][q] = 0.0f;

    for (int kt = 0; kt < 8; kt++) {
        __syncthreads();
#pragma unroll
        for (int p = 0; p < 4; p++) {
            int idx  = p * 256 + tid;
            int row  = idx >> 3;
            int colq = idx & 7;
            int grow = row0 + row;
            float4 v = make_float4(0.f, 0.f, 0.f, 0.f);
            if (grow < NV) {
                if (kt < 4) {
                    v = *reinterpret_cast<const float4*>(
                        g_agg + (size_t)grow * H + kt * BK + colq * 4);
                } else {
                    v = *reinterpret_cast<const float4*>(
                        x + (size_t)grow * H + (kt - 4) * BK + colq * 4);
                    float dg = (float)(g_rowptr[grow + 1] - g_rowptr[grow]);
                    v.x *= dg; v.y *= dg; v.z *= dg; v.w *= dg;
                }
            }
            float hx = __bfloat162float(__float2bfloat16(v.x));
            float hy = __bfloat162float(__float2bfloat16(v.y));
            float hz = __bfloat162float(__float2bfloat16(v.z));
            float hw = __bfloat162float(__float2bfloat16(v.w));
            uint2 hp = make_uint2(pack_bf2(hx, hy), pack_bf2(hz, hw));
            uint2 lp = make_uint2(pack_bf2(v.x - hx, v.y - hy),
                                  pack_bf2(v.z - hz, v.w - hw));
            *reinterpret_cast<uint2*>(&Ahi[row][colq * 4]) = hp;
            *reinterpret_cast<uint2*>(&Alo[row][colq * 4]) = lp;
        }
#pragma unroll
        for (int p = 0; p < 4; p++) {
            int idx  = p * 256 + tid;
            int n    = idx >> 3;
            int colq = idx & 7;
            float4 v = *reinterpret_cast<const float4*>(
                W + (size_t)n * (2 * H) + kt * BK + colq * 4);
            float hx = __bfloat162float(__float2bfloat16(v.x));
            float hy = __bfloat162float(__float2bfloat16(v.y));
            float hz = __bfloat162float(__float2bfloat16(v.z));
            float hw = __bfloat162float(__float2bfloat16(v.w));
            uint2 hp = make_uint2(pack_bf2(hx, hy), pack_bf2(hz, hw));
            uint2 lp = make_uint2(pack_bf2(v.x - hx, v.y - hy),
                                  pack_bf2(v.z - hz, v.w - hw));
            *reinterpret_cast<uint2*>(&Bhi[n][colq * 4]) = hp;
            *reinterpret_cast<uint2*>(&Blo[n][colq * 4]) = lp;
        }
        __syncthreads();

#pragma unroll
        for (int ks = 0; ks < 2; ks++) {
            int kb = ks * 16 + tig * 2;
            uint32_t ah[2][4], al[2][4];
#pragma unroll
            for (int mi = 0; mi < 2; mi++) {
                int r = warp_m * 32 + mi * 16 + grp;
                ah[mi][0] = *reinterpret_cast<const uint32_t*>(&Ahi[r][kb]);
                ah[mi][1] = *reinterpret_cast<const uint32_t*>(&Ahi[r + 8][kb]);
                ah[mi][2] = *reinterpret_cast<const uint32_t*>(&Ahi[r][kb + 8]);
                ah[mi][3] = *reinterpret_cast<const uint32_t*>(&Ahi[r + 8][kb + 8]);
                al[mi][0] = *reinterpret_cast<const uint32_t*>(&Alo[r][kb]);
                al[mi][1] = *reinterpret_cast<const uint32_t*>(&Alo[r + 8][kb]);
                al[mi][2] = *reinterpret_cast<const uint32_t*>(&Alo[r][kb + 8]);
                al[mi][3] = *reinterpret_cast<const uint32_t*>(&Alo[r + 8][kb + 8]);
            }
#pragma unroll
            for (int ni = 0; ni < 8; ni++) {
                int n = warp_n * 64 + ni * 8 + grp;
                uint32_t bh0 = *reinterpret_cast<const uint32_t*>(&Bhi[n][kb]);
                uint32_t bh1 = *reinterpret_cast<const uint32_t*>(&Bhi[n][kb + 8]);
                uint32_t bl0 = *reinterpret_cast<const uint32_t*>(&Blo[n][kb]);
                uint32_t bl1 = *reinterpret_cast<const uint32_t*>(&Blo[n][kb + 8]);
#pragma unroll
                for (int mi = 0; mi < 2; mi++) {
                    mma_16816(acc[mi][ni], ah[mi], bh0, bh1);
                    mma_16816(acc[mi][ni], ah[mi], bl0, bl1);
                    mma_16816(acc[mi][ni], al[mi], bh0, bh1);
                }
            }
        }
    }

#pragma unroll
    for (int mi = 0; mi < 2; mi++) {
        int r0 = row0 + warp_m * 32 + mi * 16 + grp;
#pragma unroll
        for (int ni = 0; ni < 8; ni++) {
            int col = warp_n * 64 + ni * 8 + tig * 2;
            if (r0 < NV)
                *reinterpret_cast<float2*>(out + (size_t)r0 * H + col) =
                    make_float2(acc[mi][ni][0], acc[mi][ni][1]);
            if (r0 + 8 < NV)
                *reinterpret_cast<float2*>(out + (size_t)(r0 + 8) * H + col) =
                    make_float2(acc[mi][ni][2], acc[mi][ni][3]);
        }
    }
}

// ---------------------------------------------------------------------------
extern "C" void kernel_launch(void* const* d_in, const int* in_sizes, int n_in,
                              void* d_out, int out_size) {
    const float* x  = (const float*)d_in[0];   // [NV, 128] f32
    const float* W  = (const float*)d_in[1];   // [128, 256] f32
    const int*   ei = (const int*)d_in[2];     // [2, E] i32
    float* out = (float*)d_out;                // [NV, 128] f32

    int nE    = in_sizes[2] / 2;
    int total = in_sizes[2];                   // 2E endpoint entries

    k_zero_cnt<<<(NV + 255) / 256, 256>>>();
    k_hist<<<(total / 4 + 255) / 256, 256>>>(ei, total);
    k_scan<<<1, 1024>>>();
    k_fill<<<(nE + 255) / 256, 256>>>(ei, nE);
    k_gather<<<(NV * 32 + 255) / 256, 256>>>(x);
    k_gemm<<<(NV + 127) / 128, 256>>>(x, W, out);

    (void)n_in; (void)out_size;
}